// round 12
// baseline (speedup 1.0000x reference)
#include <cuda_runtime.h>
#include <cuda_fp16.h>
#include <cstdint>

// ---------------------------------------------------------------------------
// BitNetLinear (sm_103 portable path):
//   out = (x @ qw^T) * w_scale + bias * input_scale   (input_scale cancels in
//   the GEMM; x fed raw as fp16)
// GEMM M=N=K=4096: mma.sync.m16n8k16 fp16->fp32, ldmatrix.x4.
// R12 = R9 mainloop (BK=32, 4 stages, cross-barrier fragment pipelining,
// CTA 128x128 / warp 64x64, 2 CTAs/SM) + cross-CTA split-K/2:
// 2048 CTAs (6.92 waves vs 3.46 -> 98.9% vs 86.5% wave utilization),
// second-arriver merge via per-tile atomic flag (deadlock-free, no spin).
// ---------------------------------------------------------------------------

#define NELEM 16777216   // 4096*4096
#define KTOT  4096
#define KHALF 2048
#define BM 128
#define BN 128
#define BK 32
#define STAGES 4
#define ROWB 80          // 32 halves = 64B + 16B pad (conflict-free ldmatrix)
#define STAGE_BYTES ((BM + BN) * ROWB)   // 20480; x4 = 81920; x2 CTA = 160KB
#define NKT (KHALF / BK) // 64

// Scratch (__device__ globals: allocation-free rule)
__device__ __align__(128) __half g_xh[(size_t)NELEM];   // x as fp16
__device__ __align__(128) __half g_qwh[(size_t)NELEM];  // ternary weight, fp16
__device__ __align__(128) float  g_pt[2][(size_t)1024 * 16384];  // splitK partials
__device__ int   g_flag[1024];
__device__ float g_part[2048];
__device__ float g_scales[2];   // [0]=input_scale, [1]=w_scale

// ------------------------------ helpers -----------------------------------
__device__ __forceinline__ uint32_t smem_u32(const void* p) {
    uint32_t a;
    asm("{ .reg .u64 t; cvta.to.shared.u64 t, %1; cvt.u32.u64 %0, t; }"
        : "=r"(a) : "l"(p));
    return a;
}
__device__ __forceinline__ void cp16(uint32_t s, const void* g) {
    asm volatile("cp.async.cg.shared.global [%0], [%1], 16;" :: "r"(s), "l"(g));
}
__device__ __forceinline__ void ldmx4(uint32_t r[4], uint32_t addr) {
    asm volatile("ldmatrix.sync.aligned.m8n8.x4.shared.b16 {%0,%1,%2,%3}, [%4];"
                 : "=r"(r[0]), "=r"(r[1]), "=r"(r[2]), "=r"(r[3]) : "r"(addr));
}
__device__ __forceinline__ void mma16816(float c[4], const uint32_t a[4],
                                         uint32_t b0, uint32_t b1) {
    asm volatile(
        "mma.sync.aligned.m16n8k16.row.col.f32.f16.f16.f32 "
        "{%0,%1,%2,%3}, {%4,%5,%6,%7}, {%8,%9}, {%0,%1,%2,%3};"
        : "+f"(c[0]), "+f"(c[1]), "+f"(c[2]), "+f"(c[3])
        : "r"(a[0]), "r"(a[1]), "r"(a[2]), "r"(a[3]), "r"(b0), "r"(b1));
}

// ---------------------------------------------------------------------------
// Pass 1: abs-sum partials (fp32): x blocks 0..1023 (fused fp16 convert),
// w blocks 1024..2047.
// ---------------------------------------------------------------------------
__global__ void k_reduce(const float* __restrict__ x, const float* __restrict__ w,
                         int n4) {
    const int isW = (blockIdx.x >= 1024);
    const float4* p = (const float4*)(isW ? w : x);
    __half2* q = (__half2*)g_xh;
    const int b0 = isW ? (blockIdx.x - 1024) : blockIdx.x;
    float s0 = 0.f, s1 = 0.f, s2 = 0.f, s3 = 0.f;
    for (int i = b0 * blockDim.x + threadIdx.x; i < n4; i += 1024 * blockDim.x) {
        float4 v = p[i];
        s0 += fabsf(v.x); s1 += fabsf(v.y); s2 += fabsf(v.z); s3 += fabsf(v.w);
        if (!isW) {
            q[2 * i]     = __floats2half2_rn(v.x, v.y);
            q[2 * i + 1] = __floats2half2_rn(v.z, v.w);
        }
    }
    __shared__ float smd[256];
    smd[threadIdx.x] = (s0 + s1) + (s2 + s3);
    __syncthreads();
    for (int o = 128; o > 0; o >>= 1) {
        if (threadIdx.x < o) smd[threadIdx.x] += smd[threadIdx.x + o];
        __syncthreads();
    }
    if (threadIdx.x == 0) g_part[blockIdx.x] = smd[0];
}

// ---------------------------------------------------------------------------
// Pass 2: quantize. Each block derives w_scale from the partials itself
// (bitwise identical across blocks). Block 0 publishes both scales.
// ---------------------------------------------------------------------------
__global__ void k_quant(const float* __restrict__ w, int n4) {
    __shared__ float smd[256];
    const int tid = threadIdx.x;
    float sw = 0.f;
    for (int i = tid; i < 1024; i += 256) sw += g_part[1024 + i];
    smd[tid] = sw;
    __syncthreads();
    for (int o = 128; o > 0; o >>= 1) {
        if (tid < o) smd[tid] += smd[tid + o];
        __syncthreads();
    }
    const float s = fmaxf(smd[0] / (float)NELEM, 1e-8f);

    if (blockIdx.x == 0) {
        __syncthreads();
        float sx = 0.f;
        for (int i = tid; i < 1024; i += 256) sx += g_part[i];
        smd[tid] = sx;
        __syncthreads();
        for (int o = 128; o > 0; o >>= 1) {
            if (tid < o) smd[tid] += smd[tid + o];
            __syncthreads();
        }
        if (tid == 0) {
            g_scales[0] = fmaxf(smd[0] / (float)NELEM, 1e-8f);
            g_scales[1] = s;
        }
    }

    const __half one = __float2half(1.0f), mone = __float2half(-1.0f),
                 zero = __float2half(0.0f);
    const float4* p = (const float4*)w;
    __half2* q = (__half2*)g_qwh;
    for (int i = blockIdx.x * blockDim.x + tid; i < n4;
         i += gridDim.x * blockDim.x) {
        float4 v = p[i];
        __half h0 = (fabsf(v.x / s) > 0.5f) ? (v.x > 0.f ? one : mone) : zero;
        __half h1 = (fabsf(v.y / s) > 0.5f) ? (v.y > 0.f ? one : mone) : zero;
        __half h2 = (fabsf(v.z / s) > 0.5f) ? (v.z > 0.f ? one : mone) : zero;
        __half h3 = (fabsf(v.w / s) > 0.5f) ? (v.w > 0.f ? one : mone) : zero;
        q[2 * i]     = __halves2half2(h0, h1);
        q[2 * i + 1] = __halves2half2(h2, h3);
    }
}

// ---------------------------------------------------------------------------
// Pass 3: GEMM, split-K/2.  grid (64, 32): bx = ntile*2 + kh (pairs adjacent),
// by = mtile.  Each CTA: 128x128 tile over K-half kh.  Mainloop = R9.
// Merge: store fp32 partial to g_pt[kh], fence, atomicAdd(flag); second
// arriver adds partner partial (commutative -> deterministic) + scale/bias.
// ---------------------------------------------------------------------------
__global__ void __launch_bounds__(128, 2)
k_gemm(const float* __restrict__ bias, float* __restrict__ out) {
    extern __shared__ char smem[];
    const uint32_t sb = smem_u32(smem);

    const int tid  = threadIdx.x;
    const int warp = tid >> 5, lane = tid & 31;
    const int kh = blockIdx.x & 1, ntile = blockIdx.x >> 1;
    const int m0 = blockIdx.y * BM, n0 = ntile * BN;
    const int tile = blockIdx.y * 32 + ntile;
    const int wm = (warp >> 1) * 64;   // 0 or 64
    const int wn = (warp & 1) * 64;    // 0 or 64
    const int grp = lane >> 2, tig = lane & 3;

    float acc[4][8][4];
#pragma unroll
    for (int i = 0; i < 4; i++)
#pragma unroll
        for (int j = 0; j < 8; j++)
#pragma unroll
            for (int r = 0; r < 4; r++) acc[i][j][r] = 0.f;

    // gmem: 16B chunks, row stride 512 chunks; K-half offset = kh*256 chunks
    const uint4* gA = (const uint4*)(g_xh  + (size_t)m0 * KTOT);
    const uint4* gB = (const uint4*)(g_qwh + (size_t)n0 * KTOT);
    const int kbase = kh * 256;

    const int lr = tid >> 2, lc = tid & 3;   // 4 sweeps of 32 rows

    auto issue = [&](int kt, int buf) {
        const uint32_t bA = sb + buf * STAGE_BYTES;
        const uint32_t bB = bA + BM * ROWB;
        const size_t gcol = (size_t)kbase + kt * 4 + lc;
#pragma unroll
        for (int i = 0; i < 4; i++) {
            const int r = lr + i * 32;
            cp16(bA + r * ROWB + lc * 16, gA + (size_t)r * 512 + gcol);
            cp16(bB + r * ROWB + lc * 16, gB + (size_t)r * 512 + gcol);
        }
    };

    const int lrow = lane & 15, lsel = lane >> 4;

    uint32_t a[2][4][4], b[2][4][4];

    auto loadFrag = [&](int buf, int ks, int pb) {
        const uint32_t bA = sb + buf * STAGE_BYTES;
        const uint32_t bB = bA + BM * ROWB;
        const uint32_t kcol = (uint32_t)(ks * 2 + lsel) * 16;
#pragma unroll
        for (int mi = 0; mi < 4; mi++)
            ldmx4(a[pb][mi], bA + (uint32_t)(wm + mi * 16 + lrow) * ROWB + kcol);
#pragma unroll
        for (int bi = 0; bi < 4; bi++)
            ldmx4(b[pb][bi], bB + (uint32_t)(wn + bi * 16 + lrow) * ROWB + kcol);
    };
    auto mmaStep = [&](int pb) {
#pragma unroll
        for (int mi = 0; mi < 4; mi++)
#pragma unroll
            for (int bi = 0; bi < 4; bi++) {
                mma16816(acc[mi][2 * bi],     a[pb][mi], b[pb][bi][0], b[pb][bi][2]);
                mma16816(acc[mi][2 * bi + 1], a[pb][mi], b[pb][bi][1], b[pb][bi][3]);
            }
    };

    // prologue: stages 0..2 in flight; stage 0 resident; ks0 frags loaded
    issue(0, 0);
    asm volatile("cp.async.commit_group;" ::: "memory");
    issue(1, 1);
    asm volatile("cp.async.commit_group;" ::: "memory");
    issue(2, 2);
    asm volatile("cp.async.commit_group;" ::: "memory");
    asm volatile("cp.async.wait_group 2;" ::: "memory");
    __syncthreads();
    loadFrag(0, 0, 0);

    for (int kt = 0; kt < NKT; kt++) {
        const int cur = kt & 3;

        loadFrag(cur, 1, 1);               // ks1 frags (current stage)
        mmaStep(0);                        // HMMA ks0
        if (kt + 3 < NKT) issue(kt + 3, (kt + 3) & 3);
        asm volatile("cp.async.commit_group;" ::: "memory");
        asm volatile("cp.async.wait_group 2;" ::: "memory");
        __syncthreads();                   // stage kt+1 resident
        if (kt + 1 < NKT) loadFrag((kt + 1) & 3, 0, 0);  // next tile ks0
        mmaStep(1);                        //   hidden under ks1 HMMA block
    }

    // -------------------- split-K merge --------------------
    float* gp = g_pt[kh] + (size_t)tile * 16384;
#pragma unroll
    for (int mi = 0; mi < 4; mi++) {
        const int ml = wm + mi * 16 + grp;
#pragma unroll
        for (int ni = 0; ni < 8; ni++) {
            const int nl = wn + ni * 8 + tig * 2;
            *(float2*)&gp[ml * 128 + nl]       = make_float2(acc[mi][ni][0], acc[mi][ni][1]);
            *(float2*)&gp[(ml + 8) * 128 + nl] = make_float2(acc[mi][ni][2], acc[mi][ni][3]);
        }
    }
    __threadfence();
    __syncthreads();
    __shared__ int s_old;
    if (tid == 0) s_old = atomicAdd(&g_flag[tile], 1);
    __syncthreads();
    if (s_old == 0) return;                // first arriver: partner will merge

    // second arriver: add partner partial (fp add commutative -> deterministic)
    const float* pp = g_pt[kh ^ 1] + (size_t)tile * 16384;
    const float ws = g_scales[1], is = g_scales[0];
#pragma unroll
    for (int mi = 0; mi < 4; mi++) {
        const int ml = wm + mi * 16 + grp;
        const int m = m0 + ml;
#pragma unroll
        for (int ni = 0; ni < 8; ni++) {
            const int nl = wn + ni * 8 + tig * 2;
            const int n = n0 + nl;
            const float2 bv = *(const float2*)&bias[n];
            const float2 p0 = __ldcg((const float2*)&pp[ml * 128 + nl]);
            const float2 p1 = __ldcg((const float2*)&pp[(ml + 8) * 128 + nl]);
            float2 o0, o1;
            o0.x = (acc[mi][ni][0] + p0.x) * ws + bv.x * is;
            o0.y = (acc[mi][ni][1] + p0.y) * ws + bv.y * is;
            o1.x = (acc[mi][ni][2] + p1.x) * ws + bv.x * is;
            o1.y = (acc[mi][ni][3] + p1.y) * ws + bv.y * is;
            *(float2*)&out[(size_t)m * 4096 + n]       = o0;
            *(float2*)&out[(size_t)(m + 8) * 4096 + n] = o1;
        }
    }
}

// ---------------------------------------------------------------------------
extern "C" void kernel_launch(void* const* d_in, const int* in_sizes, int n_in,
                              void* d_out, int out_size) {
    const float* x    = (const float*)d_in[0];
    const float* w    = (const float*)d_in[1];
    const float* bias = (const float*)d_in[2];
    float* out = (float*)d_out;

    const int n4 = NELEM / 4;
    const int SMEM_BYTES = STAGES * STAGE_BYTES;  // 81920 (x2 CTAs = 160KB/SM)

    cudaFuncSetAttribute(k_gemm, cudaFuncAttributeMaxDynamicSharedMemorySize,
                         SMEM_BYTES);

    // reset per-tile merge flags (graph-captured memset node, default stream)
    void* fp = nullptr;
    cudaGetSymbolAddress(&fp, g_flag);
    cudaMemsetAsync(fp, 0, 1024 * sizeof(int));

    k_reduce<<<2048, 256>>>(x, w, n4);
    k_quant<<<4096, 256>>>(w, n4);

    dim3 grid(64, 32);  // bx = ntile*2 + kh, by = mtile -> 2048 CTAs
    k_gemm<<<grid, 128, SMEM_BYTES>>>(bias, out);
}

// round 13
// speedup vs baseline: 1.0372x; 1.0372x over previous
#include <cuda_runtime.h>
#include <cuda_fp16.h>
#include <cstdint>

// ---------------------------------------------------------------------------
// BitNetLinear (sm_103 portable path):
//   out = (x @ qw^T) * w_scale + bias * input_scale   (input_scale cancels in
//   the GEMM; x fed raw as fp16)
// GEMM M=N=K=4096: mma.sync.m16n8k16 fp16->fp32, ldmatrix.x4,
// CTA 128x128 / warp 64x64, BK=32, 4 stages, 2 CTAs/SM (R9 mainloop).
// R13: PARTIAL-WAVE split-K. Tiles 0..887 (exactly 3 full waves of 296
// slots) run full-K as in R9. The last 136 tiles are split into 272 half-K
// CTAs forming a ~half-duration 4th wave (makespan ~3.5 vs 4 waves).
// Merge cost only for those 136 tiles (~5us vs R12's ~65us for all 1024).
// ---------------------------------------------------------------------------

#define NELEM 16777216   // 4096*4096
#define KTOT  4096
#define BM 128
#define BN 128
#define BK 32
#define STAGES 4
#define ROWB 80          // 32 halves = 64B + 16B pad (conflict-free ldmatrix)
#define STAGE_BYTES ((BM + BN) * ROWB)   // 20480; x4 = 81920; x2 CTA = 160KB
#define FULL_TILES 888   // 3 x 296 (148 SMs x 2 CTAs)
#define SPLIT_TILES 136  // tiles 888..1023, split-K/2
#define TOTAL_CTAS (FULL_TILES + 2 * SPLIT_TILES)  // 1160

// Scratch (__device__ globals: allocation-free rule)
__device__ __align__(128) __half g_xh[(size_t)NELEM];   // x as fp16
__device__ __align__(128) __half g_qwh[(size_t)NELEM];  // ternary weight, fp16
__device__ __align__(128) float  g_pt[(size_t)SPLIT_TILES * 2 * 16384];
__device__ int   g_flag[SPLIT_TILES];
__device__ float g_part[2048];
__device__ float g_scales[2];   // [0]=input_scale, [1]=w_scale

// ------------------------------ helpers -----------------------------------
__device__ __forceinline__ uint32_t smem_u32(const void* p) {
    uint32_t a;
    asm("{ .reg .u64 t; cvta.to.shared.u64 t, %1; cvt.u32.u64 %0, t; }"
        : "=r"(a) : "l"(p));
    return a;
}
__device__ __forceinline__ void cp16(uint32_t s, const void* g) {
    asm volatile("cp.async.cg.shared.global [%0], [%1], 16;" :: "r"(s), "l"(g));
}
__device__ __forceinline__ void ldmx4(uint32_t r[4], uint32_t addr) {
    asm volatile("ldmatrix.sync.aligned.m8n8.x4.shared.b16 {%0,%1,%2,%3}, [%4];"
                 : "=r"(r[0]), "=r"(r[1]), "=r"(r[2]), "=r"(r[3]) : "r"(addr));
}
__device__ __forceinline__ void mma16816(float c[4], const uint32_t a[4],
                                         uint32_t b0, uint32_t b1) {
    asm volatile(
        "mma.sync.aligned.m16n8k16.row.col.f32.f16.f16.f32 "
        "{%0,%1,%2,%3}, {%4,%5,%6,%7}, {%8,%9}, {%0,%1,%2,%3};"
        : "+f"(c[0]), "+f"(c[1]), "+f"(c[2]), "+f"(c[3])
        : "r"(a[0]), "r"(a[1]), "r"(a[2]), "r"(a[3]), "r"(b0), "r"(b1));
}

// ---------------------------------------------------------------------------
// Pass 1: abs-sum partials (fp32): x blocks 0..1023 (fused fp16 convert),
// w blocks 1024..2047.
// ---------------------------------------------------------------------------
__global__ void k_reduce(const float* __restrict__ x, const float* __restrict__ w,
                         int n4) {
    const int isW = (blockIdx.x >= 1024);
    const float4* p = (const float4*)(isW ? w : x);
    __half2* q = (__half2*)g_xh;
    const int b0 = isW ? (blockIdx.x - 1024) : blockIdx.x;
    float s0 = 0.f, s1 = 0.f, s2 = 0.f, s3 = 0.f;
    for (int i = b0 * blockDim.x + threadIdx.x; i < n4; i += 1024 * blockDim.x) {
        float4 v = p[i];
        s0 += fabsf(v.x); s1 += fabsf(v.y); s2 += fabsf(v.z); s3 += fabsf(v.w);
        if (!isW) {
            q[2 * i]     = __floats2half2_rn(v.x, v.y);
            q[2 * i + 1] = __floats2half2_rn(v.z, v.w);
        }
    }
    __shared__ float smd[256];
    smd[threadIdx.x] = (s0 + s1) + (s2 + s3);
    __syncthreads();
    for (int o = 128; o > 0; o >>= 1) {
        if (threadIdx.x < o) smd[threadIdx.x] += smd[threadIdx.x + o];
        __syncthreads();
    }
    if (threadIdx.x == 0) g_part[blockIdx.x] = smd[0];
}

// ---------------------------------------------------------------------------
// Pass 2: quantize. Each block derives w_scale from the partials itself
// (bitwise identical across blocks). Block 0 publishes both scales.
// ---------------------------------------------------------------------------
__global__ void k_quant(const float* __restrict__ w, int n4) {
    __shared__ float smd[256];
    const int tid = threadIdx.x;
    float sw = 0.f;
    for (int i = tid; i < 1024; i += 256) sw += g_part[1024 + i];
    smd[tid] = sw;
    __syncthreads();
    for (int o = 128; o > 0; o >>= 1) {
        if (tid < o) smd[tid] += smd[tid + o];
        __syncthreads();
    }
    const float s = fmaxf(smd[0] / (float)NELEM, 1e-8f);

    if (blockIdx.x == 0) {
        __syncthreads();
        float sx = 0.f;
        for (int i = tid; i < 1024; i += 256) sx += g_part[i];
        smd[tid] = sx;
        __syncthreads();
        for (int o = 128; o > 0; o >>= 1) {
            if (tid < o) smd[tid] += smd[tid + o];
            __syncthreads();
        }
        if (tid == 0) {
            g_scales[0] = fmaxf(smd[0] / (float)NELEM, 1e-8f);
            g_scales[1] = s;
        }
    }

    const __half one = __float2half(1.0f), mone = __float2half(-1.0f),
                 zero = __float2half(0.0f);
    const float4* p = (const float4*)w;
    __half2* q = (__half2*)g_qwh;
    for (int i = blockIdx.x * blockDim.x + tid; i < n4;
         i += gridDim.x * blockDim.x) {
        float4 v = p[i];
        __half h0 = (fabsf(v.x / s) > 0.5f) ? (v.x > 0.f ? one : mone) : zero;
        __half h1 = (fabsf(v.y / s) > 0.5f) ? (v.y > 0.f ? one : mone) : zero;
        __half h2 = (fabsf(v.z / s) > 0.5f) ? (v.z > 0.f ? one : mone) : zero;
        __half h3 = (fabsf(v.w / s) > 0.5f) ? (v.w > 0.f ? one : mone) : zero;
        q[2 * i]     = __halves2half2(h0, h1);
        q[2 * i + 1] = __halves2half2(h2, h3);
    }
}

// ---------------------------------------------------------------------------
// Pass 3: GEMM, 1D grid of 1160 CTAs.
//   bid <  888 : full-K tile, tile = bid             (3 exact waves)
//   bid >= 888 : sid = bid-888; tile = 888 + sid/2; kh = sid&1  (half wave)
// tile -> m0 = (tile>>5)*128, n0 = (tile&31)*128.
// Mainloop = R9 (BK=32, 4 stages, cross-barrier fragment pipelining).
// ---------------------------------------------------------------------------
__global__ void __launch_bounds__(128, 2)
k_gemm(const float* __restrict__ bias, float* __restrict__ out) {
    extern __shared__ char smem[];
    const uint32_t sb = smem_u32(smem);

    const int tid  = threadIdx.x;
    const int warp = tid >> 5, lane = tid & 31;

    int tile, kh, nkt, stile;
    if (blockIdx.x < FULL_TILES) {
        tile = blockIdx.x; kh = 0; nkt = 128; stile = -1;
    } else {
        const int sid = blockIdx.x - FULL_TILES;
        stile = sid >> 1;
        tile = FULL_TILES + stile;
        kh = sid & 1;
        nkt = 64;
    }
    const int m0 = (tile >> 5) * BM, n0 = (tile & 31) * BN;
    const int wm = (warp >> 1) * 64;   // 0 or 64
    const int wn = (warp & 1) * 64;    // 0 or 64
    const int grp = lane >> 2, tig = lane & 3;

    float acc[4][8][4];
#pragma unroll
    for (int i = 0; i < 4; i++)
#pragma unroll
        for (int j = 0; j < 8; j++)
#pragma unroll
            for (int r = 0; r < 4; r++) acc[i][j][r] = 0.f;

    // gmem: 16B chunks, row stride 512 chunks; K-half offset = kh*256 chunks
    const uint4* gA = (const uint4*)(g_xh  + (size_t)m0 * KTOT);
    const uint4* gB = (const uint4*)(g_qwh + (size_t)n0 * KTOT);
    const int kbase = kh * 256;

    const int lr = tid >> 2, lc = tid & 3;   // 4 sweeps of 32 rows

    auto issue = [&](int kt, int buf) {
        const uint32_t bA = sb + buf * STAGE_BYTES;
        const uint32_t bB = bA + BM * ROWB;
        const size_t gcol = (size_t)kbase + kt * 4 + lc;
#pragma unroll
        for (int i = 0; i < 4; i++) {
            const int r = lr + i * 32;
            cp16(bA + r * ROWB + lc * 16, gA + (size_t)r * 512 + gcol);
            cp16(bB + r * ROWB + lc * 16, gB + (size_t)r * 512 + gcol);
        }
    };

    const int lrow = lane & 15, lsel = lane >> 4;

    uint32_t a[2][4][4], b[2][4][4];  // k-step parity double-buffered fragments

    auto loadFrag = [&](int buf, int ks, int pb) {
        const uint32_t bA = sb + buf * STAGE_BYTES;
        const uint32_t bB = bA + BM * ROWB;
        const uint32_t kcol = (uint32_t)(ks * 2 + lsel) * 16;
#pragma unroll
        for (int mi = 0; mi < 4; mi++)
            ldmx4(a[pb][mi], bA + (uint32_t)(wm + mi * 16 + lrow) * ROWB + kcol);
#pragma unroll
        for (int bi = 0; bi < 4; bi++)
            ldmx4(b[pb][bi], bB + (uint32_t)(wn + bi * 16 + lrow) * ROWB + kcol);
    };
    auto mmaStep = [&](int pb) {
#pragma unroll
        for (int mi = 0; mi < 4; mi++)
#pragma unroll
            for (int bi = 0; bi < 4; bi++) {
                mma16816(acc[mi][2 * bi],     a[pb][mi], b[pb][bi][0], b[pb][bi][2]);
                mma16816(acc[mi][2 * bi + 1], a[pb][mi], b[pb][bi][1], b[pb][bi][3]);
            }
    };

    // prologue: stages 0..2 in flight; stage 0 resident; ks0 frags loaded
    issue(0, 0);
    asm volatile("cp.async.commit_group;" ::: "memory");
    issue(1, 1);
    asm volatile("cp.async.commit_group;" ::: "memory");
    issue(2, 2);
    asm volatile("cp.async.commit_group;" ::: "memory");
    asm volatile("cp.async.wait_group 2;" ::: "memory");
    __syncthreads();
    loadFrag(0, 0, 0);

    for (int kt = 0; kt < nkt; kt++) {
        const int cur = kt & 3;

        loadFrag(cur, 1, 1);               // ks1 frags (current stage)
        mmaStep(0);                        // HMMA ks0
        if (kt + 3 < nkt) issue(kt + 3, (kt + 3) & 3);
        asm volatile("cp.async.commit_group;" ::: "memory");
        asm volatile("cp.async.wait_group 2;" ::: "memory");
        __syncthreads();                   // stage kt+1 resident
        if (kt + 1 < nkt) loadFrag((kt + 1) & 3, 0, 0);  // next tile ks0
        mmaStep(1);                        //   hidden under ks1 HMMA block
    }

    const float ws = g_scales[1], is = g_scales[0];

    if (stile < 0) {
        // ---------------- full-K epilogue (R9) ----------------
#pragma unroll
        for (int mi = 0; mi < 4; mi++) {
            const int m = m0 + wm + mi * 16 + grp;
#pragma unroll
            for (int ni = 0; ni < 8; ni++) {
                const int n = n0 + wn + ni * 8 + tig * 2;
                const float2 bv = *(const float2*)&bias[n];
                float2 o0, o1;
                o0.x = acc[mi][ni][0] * ws + bv.x * is;
                o0.y = acc[mi][ni][1] * ws + bv.y * is;
                o1.x = acc[mi][ni][2] * ws + bv.x * is;
                o1.y = acc[mi][ni][3] * ws + bv.y * is;
                *(float2*)&out[(size_t)m * 4096 + n]       = o0;
                *(float2*)&out[(size_t)(m + 8) * 4096 + n] = o1;
            }
        }
        return;
    }

    // ---------------- split-K merge (second arriver) ----------------
    float* gp = g_pt + ((size_t)stile * 2 + kh) * 16384;
#pragma unroll
    for (int mi = 0; mi < 4; mi++) {
        const int ml = wm + mi * 16 + grp;
#pragma unroll
        for (int ni = 0; ni < 8; ni++) {
            const int nl = wn + ni * 8 + tig * 2;
            *(float2*)&gp[ml * 128 + nl]       = make_float2(acc[mi][ni][0], acc[mi][ni][1]);
            *(float2*)&gp[(ml + 8) * 128 + nl] = make_float2(acc[mi][ni][2], acc[mi][ni][3]);
        }
    }
    __threadfence();
    __syncthreads();
    __shared__ int s_old;
    if (tid == 0) s_old = atomicAdd(&g_flag[stile], 1);
    __syncthreads();
    if (s_old == 0) return;                // first arriver: partner merges

    const float* pp = g_pt + ((size_t)stile * 2 + (kh ^ 1)) * 16384;
#pragma unroll
    for (int mi = 0; mi < 4; mi++) {
        const int ml = wm + mi * 16 + grp;
        const int m = m0 + ml;
#pragma unroll
        for (int ni = 0; ni < 8; ni++) {
            const int nl = wn + ni * 8 + tig * 2;
            const int n = n0 + nl;
            const float2 bv = *(const float2*)&bias[n];
            const float2 p0 = __ldcg((const float2*)&pp[ml * 128 + nl]);
            const float2 p1 = __ldcg((const float2*)&pp[(ml + 8) * 128 + nl]);
            float2 o0, o1;
            o0.x = (acc[mi][ni][0] + p0.x) * ws + bv.x * is;
            o0.y = (acc[mi][ni][1] + p0.y) * ws + bv.y * is;
            o1.x = (acc[mi][ni][2] + p1.x) * ws + bv.x * is;
            o1.y = (acc[mi][ni][3] + p1.y) * ws + bv.y * is;
            *(float2*)&out[(size_t)m * 4096 + n]       = o0;
            *(float2*)&out[(size_t)(m + 8) * 4096 + n] = o1;
        }
    }
}

// ---------------------------------------------------------------------------
extern "C" void kernel_launch(void* const* d_in, const int* in_sizes, int n_in,
                              void* d_out, int out_size) {
    const float* x    = (const float*)d_in[0];
    const float* w    = (const float*)d_in[1];
    const float* bias = (const float*)d_in[2];
    float* out = (float*)d_out;

    const int n4 = NELEM / 4;
    const int SMEM_BYTES = STAGES * STAGE_BYTES;  // 81920 (x2 CTAs = 160KB/SM)

    cudaFuncSetAttribute(k_gemm, cudaFuncAttributeMaxDynamicSharedMemorySize,
                         SMEM_BYTES);

    // reset per-split-tile merge flags (graph-captured memset node)
    void* fp = nullptr;
    cudaGetSymbolAddress(&fp, g_flag);
    cudaMemsetAsync(fp, 0, SPLIT_TILES * sizeof(int));

    k_reduce<<<2048, 256>>>(x, w, n4);
    k_quant<<<2048, 256>>>(w, n4);

    k_gemm<<<TOTAL_CTAS, 128, SMEM_BYTES>>>(bias, out);
}

// round 14
// speedup vs baseline: 1.1109x; 1.0710x over previous
#include <cuda_runtime.h>
#include <cuda_fp16.h>
#include <cstdint>

// ---------------------------------------------------------------------------
// BitNetLinear (sm_103 portable path):
//   out = (x @ qw^T) * w_scale + bias * input_scale   (input_scale cancels in
//   the GEMM; x fed raw as fp16)
// GEMM M=N=K=4096: mma.sync.m16n8k16 fp16->fp32, ldmatrix.x4.
// R14: two-launch wave-tail fix, R9 mainloop untouched.
//   Launch 1: k_gemm  — EXACT R9 kernel on tiles 0..887 (= 3 full waves).
//   Launch 2: k_gemm_tail — last 136 tiles split by N into 272 CTAs of
//             128x64 (one ~half-duration wave). Full-K sums -> no merge,
//             no atomics, bitwise-identical numerics.
// ---------------------------------------------------------------------------

#define NELEM 16777216   // 4096*4096
#define KTOT  4096
#define BM 128
#define BN 128
#define BK 32
#define STAGES 4
#define ROWB 80          // 32 halves = 64B + 16B pad (conflict-free ldmatrix)
#define STAGE_BYTES ((BM + BN) * ROWB)       // 20480; x4 = 81920
#define NKT (KTOT / BK)  // 128
#define FULL_TILES 888   // 3 x 296 (148 SMs x 2 CTAs/SM)
#define TAIL_TILES 136   // tiles 888..1023, each split into 2 N-halves
// tail kernel: 128x64 tiles
#define STAGE_T ((BM + 64) * ROWB)           // 15360; x4 = 61440

// Scratch (__device__ globals: allocation-free rule)
__device__ __align__(128) __half g_xh[(size_t)NELEM];   // x as fp16
__device__ __align__(128) __half g_qwh[(size_t)NELEM];  // ternary weight, fp16
__device__ float g_part[2048];
__device__ float g_scales[2];   // [0]=input_scale, [1]=w_scale

// ------------------------------ helpers -----------------------------------
__device__ __forceinline__ uint32_t smem_u32(const void* p) {
    uint32_t a;
    asm("{ .reg .u64 t; cvta.to.shared.u64 t, %1; cvt.u32.u64 %0, t; }"
        : "=r"(a) : "l"(p));
    return a;
}
__device__ __forceinline__ void cp16(uint32_t s, const void* g) {
    asm volatile("cp.async.cg.shared.global [%0], [%1], 16;" :: "r"(s), "l"(g));
}
__device__ __forceinline__ void ldmx4(uint32_t r[4], uint32_t addr) {
    asm volatile("ldmatrix.sync.aligned.m8n8.x4.shared.b16 {%0,%1,%2,%3}, [%4];"
                 : "=r"(r[0]), "=r"(r[1]), "=r"(r[2]), "=r"(r[3]) : "r"(addr));
}
__device__ __forceinline__ void mma16816(float c[4], const uint32_t a[4],
                                         uint32_t b0, uint32_t b1) {
    asm volatile(
        "mma.sync.aligned.m16n8k16.row.col.f32.f16.f16.f32 "
        "{%0,%1,%2,%3}, {%4,%5,%6,%7}, {%8,%9}, {%0,%1,%2,%3};"
        : "+f"(c[0]), "+f"(c[1]), "+f"(c[2]), "+f"(c[3])
        : "r"(a[0]), "r"(a[1]), "r"(a[2]), "r"(a[3]), "r"(b0), "r"(b1));
}

// ---------------------------------------------------------------------------
// Pass 1: abs-sum partials (fp32): x blocks 0..1023 (fused fp16 convert),
// w blocks 1024..2047.
// ---------------------------------------------------------------------------
__global__ void k_reduce(const float* __restrict__ x, const float* __restrict__ w,
                         int n4) {
    const int isW = (blockIdx.x >= 1024);
    const float4* p = (const float4*)(isW ? w : x);
    __half2* q = (__half2*)g_xh;
    const int b0 = isW ? (blockIdx.x - 1024) : blockIdx.x;
    float s0 = 0.f, s1 = 0.f, s2 = 0.f, s3 = 0.f;
    for (int i = b0 * blockDim.x + threadIdx.x; i < n4; i += 1024 * blockDim.x) {
        float4 v = p[i];
        s0 += fabsf(v.x); s1 += fabsf(v.y); s2 += fabsf(v.z); s3 += fabsf(v.w);
        if (!isW) {
            q[2 * i]     = __floats2half2_rn(v.x, v.y);
            q[2 * i + 1] = __floats2half2_rn(v.z, v.w);
        }
    }
    __shared__ float smd[256];
    smd[threadIdx.x] = (s0 + s1) + (s2 + s3);
    __syncthreads();
    for (int o = 128; o > 0; o >>= 1) {
        if (threadIdx.x < o) smd[threadIdx.x] += smd[threadIdx.x + o];
        __syncthreads();
    }
    if (threadIdx.x == 0) g_part[blockIdx.x] = smd[0];
}

// ---------------------------------------------------------------------------
// Pass 2: quantize. Each block derives w_scale from the partials itself
// (bitwise identical across blocks). Block 0 publishes both scales.
// ---------------------------------------------------------------------------
__global__ void k_quant(const float* __restrict__ w, int n4) {
    __shared__ float smd[256];
    const int tid = threadIdx.x;
    float sw = 0.f;
    for (int i = tid; i < 1024; i += 256) sw += g_part[1024 + i];
    smd[tid] = sw;
    __syncthreads();
    for (int o = 128; o > 0; o >>= 1) {
        if (tid < o) smd[tid] += smd[tid + o];
        __syncthreads();
    }
    const float s = fmaxf(smd[0] / (float)NELEM, 1e-8f);

    if (blockIdx.x == 0) {
        __syncthreads();
        float sx = 0.f;
        for (int i = tid; i < 1024; i += 256) sx += g_part[i];
        smd[tid] = sx;
        __syncthreads();
        for (int o = 128; o > 0; o >>= 1) {
            if (tid < o) smd[tid] += smd[tid + o];
            __syncthreads();
        }
        if (tid == 0) {
            g_scales[0] = fmaxf(smd[0] / (float)NELEM, 1e-8f);
            g_scales[1] = s;
        }
    }

    const __half one = __float2half(1.0f), mone = __float2half(-1.0f),
                 zero = __float2half(0.0f);
    const float4* p = (const float4*)w;
    __half2* q = (__half2*)g_qwh;
    for (int i = blockIdx.x * blockDim.x + tid; i < n4;
         i += gridDim.x * blockDim.x) {
        float4 v = p[i];
        __half h0 = (fabsf(v.x / s) > 0.5f) ? (v.x > 0.f ? one : mone) : zero;
        __half h1 = (fabsf(v.y / s) > 0.5f) ? (v.y > 0.f ? one : mone) : zero;
        __half h2 = (fabsf(v.z / s) > 0.5f) ? (v.z > 0.f ? one : mone) : zero;
        __half h3 = (fabsf(v.w / s) > 0.5f) ? (v.w > 0.f ? one : mone) : zero;
        q[2 * i]     = __halves2half2(h0, h1);
        q[2 * i + 1] = __halves2half2(h2, h3);
    }
}

// ---------------------------------------------------------------------------
// Pass 3a: GEMM (EXACT R9 kernel), tiles 0..887. 1D grid; tile=bid,
// m0=(tile>>5)*128, n0=(tile&31)*128 (same rasterization as R9's 2D grid).
// ---------------------------------------------------------------------------
__global__ void __launch_bounds__(128, 2)
k_gemm(const float* __restrict__ bias, float* __restrict__ out) {
    extern __shared__ char smem[];
    const uint32_t sb = smem_u32(smem);

    const int tid  = threadIdx.x;
    const int warp = tid >> 5, lane = tid & 31;
    const int m0 = (blockIdx.x >> 5) * BM, n0 = (blockIdx.x & 31) * BN;
    const int wm = (warp >> 1) * 64;   // 0 or 64
    const int wn = (warp & 1) * 64;    // 0 or 64
    const int grp = lane >> 2, tig = lane & 3;

    float acc[4][8][4];
#pragma unroll
    for (int i = 0; i < 4; i++)
#pragma unroll
        for (int j = 0; j < 8; j++)
#pragma unroll
            for (int r = 0; r < 4; r++) acc[i][j][r] = 0.f;

    const uint4* gA = (const uint4*)(g_xh  + (size_t)m0 * KTOT);
    const uint4* gB = (const uint4*)(g_qwh + (size_t)n0 * KTOT);

    const int lr = tid >> 2, lc = tid & 3;   // 4 sweeps of 32 rows

    auto issue = [&](int kt, int buf) {
        const uint32_t bA = sb + buf * STAGE_BYTES;
        const uint32_t bB = bA + BM * ROWB;
        const size_t gcol = (size_t)kt * 4 + lc;
#pragma unroll
        for (int i = 0; i < 4; i++) {
            const int r = lr + i * 32;
            cp16(bA + r * ROWB + lc * 16, gA + (size_t)r * 512 + gcol);
            cp16(bB + r * ROWB + lc * 16, gB + (size_t)r * 512 + gcol);
        }
    };

    const int lrow = lane & 15, lsel = lane >> 4;

    uint32_t a[2][4][4], b[2][4][4];

    auto loadFrag = [&](int buf, int ks, int pb) {
        const uint32_t bA = sb + buf * STAGE_BYTES;
        const uint32_t bB = bA + BM * ROWB;
        const uint32_t kcol = (uint32_t)(ks * 2 + lsel) * 16;
#pragma unroll
        for (int mi = 0; mi < 4; mi++)
            ldmx4(a[pb][mi], bA + (uint32_t)(wm + mi * 16 + lrow) * ROWB + kcol);
#pragma unroll
        for (int bi = 0; bi < 4; bi++)
            ldmx4(b[pb][bi], bB + (uint32_t)(wn + bi * 16 + lrow) * ROWB + kcol);
    };
    auto mmaStep = [&](int pb) {
#pragma unroll
        for (int mi = 0; mi < 4; mi++)
#pragma unroll
            for (int bi = 0; bi < 4; bi++) {
                mma16816(acc[mi][2 * bi],     a[pb][mi], b[pb][bi][0], b[pb][bi][2]);
                mma16816(acc[mi][2 * bi + 1], a[pb][mi], b[pb][bi][1], b[pb][bi][3]);
            }
    };

    issue(0, 0);
    asm volatile("cp.async.commit_group;" ::: "memory");
    issue(1, 1);
    asm volatile("cp.async.commit_group;" ::: "memory");
    issue(2, 2);
    asm volatile("cp.async.commit_group;" ::: "memory");
    asm volatile("cp.async.wait_group 2;" ::: "memory");
    __syncthreads();
    loadFrag(0, 0, 0);

    for (int kt = 0; kt < NKT; kt++) {
        const int cur = kt & 3;

        loadFrag(cur, 1, 1);
        mmaStep(0);
        if (kt + 3 < NKT) issue(kt + 3, (kt + 3) & 3);
        asm volatile("cp.async.commit_group;" ::: "memory");
        asm volatile("cp.async.wait_group 2;" ::: "memory");
        __syncthreads();
        if (kt + 1 < NKT) loadFrag((kt + 1) & 3, 0, 0);
        mmaStep(1);
    }

    const float ws = g_scales[1], is = g_scales[0];
#pragma unroll
    for (int mi = 0; mi < 4; mi++) {
        const int m = m0 + wm + mi * 16 + grp;
#pragma unroll
        for (int ni = 0; ni < 8; ni++) {
            const int n = n0 + wn + ni * 8 + tig * 2;
            const float2 bv = *(const float2*)&bias[n];
            float2 o0, o1;
            o0.x = acc[mi][ni][0] * ws + bv.x * is;
            o0.y = acc[mi][ni][1] * ws + bv.y * is;
            o1.x = acc[mi][ni][2] * ws + bv.x * is;
            o1.y = acc[mi][ni][3] * ws + bv.y * is;
            *(float2*)&out[(size_t)m * 4096 + n]       = o0;
            *(float2*)&out[(size_t)(m + 8) * 4096 + n] = o1;
        }
    }
}

// ---------------------------------------------------------------------------
// Pass 3b: tail GEMM, 128x64 tiles (N-split of tiles 888..1023), 272 CTAs.
// sid = bid: t = sid>>1, nh = sid&1; tile = 888 + t.
// Warp tile 64x32 (2x2 warps), same fragment-pipelined schedule. Full K ->
// no merge; output sums bitwise-identical to the full kernel's.
// ---------------------------------------------------------------------------
__global__ void __launch_bounds__(128, 2)
k_gemm_tail(const float* __restrict__ bias, float* __restrict__ out) {
    extern __shared__ char smem[];
    const uint32_t sb = smem_u32(smem);

    const int tid  = threadIdx.x;
    const int warp = tid >> 5, lane = tid & 31;
    const int tile = FULL_TILES + (blockIdx.x >> 1);
    const int nh = blockIdx.x & 1;
    const int m0 = (tile >> 5) * BM, n0 = (tile & 31) * BN + nh * 64;
    const int wm = (warp >> 1) * 64;   // 0 or 64
    const int wn = (warp & 1) * 32;    // 0 or 32
    const int grp = lane >> 2, tig = lane & 3;

    float acc[4][4][4];
#pragma unroll
    for (int i = 0; i < 4; i++)
#pragma unroll
        for (int j = 0; j < 4; j++)
#pragma unroll
            for (int r = 0; r < 4; r++) acc[i][j][r] = 0.f;

    const uint4* gA = (const uint4*)(g_xh  + (size_t)m0 * KTOT);
    const uint4* gB = (const uint4*)(g_qwh + (size_t)n0 * KTOT);

    const int lr = tid >> 2, lc = tid & 3;   // A: 4 sweeps of 32; B: 2 sweeps

    auto issue = [&](int kt, int buf) {
        const uint32_t bA = sb + buf * STAGE_T;
        const uint32_t bB = bA + BM * ROWB;
        const size_t gcol = (size_t)kt * 4 + lc;
#pragma unroll
        for (int i = 0; i < 4; i++) {
            const int r = lr + i * 32;
            cp16(bA + r * ROWB + lc * 16, gA + (size_t)r * 512 + gcol);
        }
#pragma unroll
        for (int i = 0; i < 2; i++) {
            const int r = lr + i * 32;
            cp16(bB + r * ROWB + lc * 16, gB + (size_t)r * 512 + gcol);
        }
    };

    const int lrow = lane & 15, lsel = lane >> 4;

    uint32_t a[2][4][4], b[2][2][4];

    auto loadFrag = [&](int buf, int ks, int pb) {
        const uint32_t bA = sb + buf * STAGE_T;
        const uint32_t bB = bA + BM * ROWB;
        const uint32_t kcol = (uint32_t)(ks * 2 + lsel) * 16;
#pragma unroll
        for (int mi = 0; mi < 4; mi++)
            ldmx4(a[pb][mi], bA + (uint32_t)(wm + mi * 16 + lrow) * ROWB + kcol);
#pragma unroll
        for (int bi = 0; bi < 2; bi++)
            ldmx4(b[pb][bi], bB + (uint32_t)(wn + bi * 16 + lrow) * ROWB + kcol);
    };
    auto mmaStep = [&](int pb) {
#pragma unroll
        for (int mi = 0; mi < 4; mi++) {
            mma16816(acc[mi][0], a[pb][mi], b[pb][0][0], b[pb][0][2]);
            mma16816(acc[mi][1], a[pb][mi], b[pb][0][1], b[pb][0][3]);
            mma16816(acc[mi][2], a[pb][mi], b[pb][1][0], b[pb][1][2]);
            mma16816(acc[mi][3], a[pb][mi], b[pb][1][1], b[pb][1][3]);
        }
    };

    issue(0, 0);
    asm volatile("cp.async.commit_group;" ::: "memory");
    issue(1, 1);
    asm volatile("cp.async.commit_group;" ::: "memory");
    issue(2, 2);
    asm volatile("cp.async.commit_group;" ::: "memory");
    asm volatile("cp.async.wait_group 2;" ::: "memory");
    __syncthreads();
    loadFrag(0, 0, 0);

    for (int kt = 0; kt < NKT; kt++) {
        const int cur = kt & 3;

        loadFrag(cur, 1, 1);
        mmaStep(0);
        if (kt + 3 < NKT) issue(kt + 3, (kt + 3) & 3);
        asm volatile("cp.async.commit_group;" ::: "memory");
        asm volatile("cp.async.wait_group 2;" ::: "memory");
        __syncthreads();
        if (kt + 1 < NKT) loadFrag((kt + 1) & 3, 0, 0);
        mmaStep(1);
    }

    const float ws = g_scales[1], is = g_scales[0];
#pragma unroll
    for (int mi = 0; mi < 4; mi++) {
        const int m = m0 + wm + mi * 16 + grp;
#pragma unroll
        for (int ni = 0; ni < 4; ni++) {
            const int n = n0 + wn + ni * 8 + tig * 2;
            const float2 bv = *(const float2*)&bias[n];
            float2 o0, o1;
            o0.x = acc[mi][ni][0] * ws + bv.x * is;
            o0.y = acc[mi][ni][1] * ws + bv.y * is;
            o1.x = acc[mi][ni][2] * ws + bv.x * is;
            o1.y = acc[mi][ni][3] * ws + bv.y * is;
            *(float2*)&out[(size_t)m * 4096 + n]       = o0;
            *(float2*)&out[(size_t)(m + 8) * 4096 + n] = o1;
        }
    }
}

// ---------------------------------------------------------------------------
extern "C" void kernel_launch(void* const* d_in, const int* in_sizes, int n_in,
                              void* d_out, int out_size) {
    const float* x    = (const float*)d_in[0];
    const float* w    = (const float*)d_in[1];
    const float* bias = (const float*)d_in[2];
    float* out = (float*)d_out;

    const int n4 = NELEM / 4;
    const int SMEM_FULL = STAGES * STAGE_BYTES;  // 81920
    const int SMEM_TAIL = STAGES * STAGE_T;      // 61440

    cudaFuncSetAttribute(k_gemm, cudaFuncAttributeMaxDynamicSharedMemorySize,
                         SMEM_FULL);
    cudaFuncSetAttribute(k_gemm_tail, cudaFuncAttributeMaxDynamicSharedMemorySize,
                         SMEM_TAIL);

    k_reduce<<<2048, 256>>>(x, w, n4);
    k_quant<<<2048, 256>>>(w, n4);

    k_gemm<<<FULL_TILES, 128, SMEM_FULL>>>(bias, out);           // 3 full waves
    k_gemm_tail<<<2 * TAIL_TILES, 128, SMEM_TAIL>>>(bias, out);  // ~half wave
}